// round 9
// baseline (speedup 1.0000x reference)
#include <cuda_runtime.h>
#include <cuda_fp16.h>
#include <math.h>

#define Bq   4
#define Nq   65536
#define Gq   64
#define G3q  262144          // 64^3
#define CF   32
#define HW   128
#define NPIX (HW * HW)       // 16384
#define VSC  0.05f
#define R2C  1.5625f         // 1.25^2

typedef unsigned long long ull;

// -------- device scratch (no allocations allowed) --------
// P fp16, 8 channel-chunk planes per batch: g_Ph[((b*8+c8)<<14)+pix] = 8 halves
__device__ uint4         g_Ph[(size_t)Bq * 8 * NPIX];      // 8 MB
__device__ unsigned char g_occS[(size_t)Bq * G3q];
__device__ unsigned char g_occA[(size_t)Bq * G3q];
__device__ int           g_anyNearby[Bq];
__device__ int           g_anyOccS[Bq];
__device__ int           g_anyOccA[Bq];
__device__ float         g_accum[Bq][8];

// -------- packed f32x2 helpers --------
__device__ __forceinline__ ull ffma2(ull a, ull b, ull c) {
    ull d; asm("fma.rn.f32x2 %0,%1,%2,%3;" : "=l"(d) : "l"(a), "l"(b), "l"(c)); return d;
}
__device__ __forceinline__ ull add2(ull a, ull b) {
    ull d; asm("add.rn.f32x2 %0,%1,%2;" : "=l"(d) : "l"(a), "l"(b)); return d;
}
__device__ __forceinline__ ull pack2(float lo, float hi) {
    ull d; asm("mov.b64 %0,{%1,%2};" : "=l"(d) : "f"(lo), "f"(hi)); return d;
}
__device__ __forceinline__ void unpack2(ull v, float& lo, float& hi) {
    asm("mov.b64 {%0,%1},%2;" : "=f"(lo), "=f"(hi) : "l"(v));
}

// ---------------------------------------------------------
__global__ void k_clear() {
    int i = blockIdx.x * blockDim.x + threadIdx.x;   // 0 .. 262143
    ((int*)g_occS)[i] = 0;
    ((int*)g_occA)[i] = 0;
    if (i < Bq) { g_anyNearby[i] = 0; g_anyOccS[i] = 0; g_anyOccA[i] = 0; }
    if (i < Bq * 8) ((float*)g_accum)[i] = 0.0f;
}

__device__ __forceinline__ bool is_nearby(float px, float py, float pz,
                                          float ax, float ay, float az) {
    float dx = px - ax, dy = py - ay;
    float d2xy = dx * dx + dy * dy;
    float e0 = pz - (az - 0.5f);
    float e1 = pz - az;
    float e2 = pz - (az + 0.5f);
    float m = fminf(fminf(e0 * e0, e1 * e1), e2 * e2);
    return (d2xy + m) <= R2C;
}

// fused scatter: both occupancy grids + flags (4 points/thread)
__global__ void __launch_bounds__(256) k_scatter(const float* __restrict__ points,
                                                 const float* __restrict__ pelvis) {
    int idx4 = blockIdx.x * 256 + threadIdx.x;
    int b = idx4 >> 14;
    float ax = pelvis[b * 3 + 0], ay = pelvis[b * 3 + 1], az = pelvis[b * 3 + 2];
    int v0x = (int)floorf(ax / VSC) - (Gq / 2);
    int v0y = (int)floorf(ay / VSC) - (Gq / 2);
    int v0z = (int)floorf(az / VSC) - (Gq / 2);

    const float4* pp = (const float4*)(points + (size_t)idx4 * 12);
    float4 A = pp[0], Bv = pp[1], C = pp[2];
    float P[4][3] = { {A.x, A.y, A.z}, {A.w, Bv.x, Bv.y},
                      {Bv.z, Bv.w, C.x}, {C.y, C.z, C.w} };

    bool anyNb = false, anyS = false, anyA = false;
#pragma unroll
    for (int k = 0; k < 4; ++k) {
        float px = P[k][0], py = P[k][1], pz = P[k][2];
        bool nb = is_nearby(px, py, pz, ax, ay, az);
        int lx = (int)floorf(px / VSC) - v0x;
        int ly = (int)floorf(py / VSC) - v0y;
        int lz = (int)floorf(pz / VSC) - v0z;
        bool bounds = (unsigned)lx < (unsigned)Gq && (unsigned)ly < (unsigned)Gq
                    && (unsigned)lz < (unsigned)Gq;
        int cell = (lx << 12) + (ly << 6) + lz;
        if (bounds) {
            g_occA[(size_t)b * G3q + cell] = 1;
            if (nb) g_occS[(size_t)b * G3q + cell] = 1;
        }
        anyNb |= nb; anyS |= (nb && bounds); anyA |= bounds;
    }
    unsigned mN = __ballot_sync(0xffffffffu, anyNb);
    unsigned mS = __ballot_sync(0xffffffffu, anyS);
    unsigned mA = __ballot_sync(0xffffffffu, anyA);
    if ((threadIdx.x & 31) == 0) {
        if (mN) atomicOr(&g_anyNearby[b], 1);
        if (mS) atomicOr(&g_anyOccS[b], 1);
        if (mA) atomicOr(&g_anyOccA[b], 1);
    }
}

// k_proj: one pixel per thread, all 64 channels packed-f32x2; weights in SMEM.
__global__ void __launch_bounds__(256) k_proj(const float* __restrict__ fmap,
                                              const float* __restrict__ W1) {
    __shared__ ull sW[CF][32];   // sW[c][p] = (W1[3+c, 2p], W1[3+c, 2p+1])
    int t = threadIdx.x;
    for (int i = t; i < CF * 32; i += 256) {
        int c = i >> 5, p = i & 31;
        sW[c][p] = pack2(W1[(3 + c) * 64 + 2 * p], W1[(3 + c) * 64 + 2 * p + 1]);
    }
    __syncthreads();

    int idx = blockIdx.x * 256 + t;          // B*NPIX threads
    int pix = idx & (NPIX - 1);
    int b   = idx >> 14;
    const float* fp = fmap + (size_t)b * CF * NPIX + pix;

    ull acc2[32];
#pragma unroll
    for (int p = 0; p < 32; ++p) acc2[p] = 0ull;

#pragma unroll 4
    for (int c = 0; c < CF; ++c) {
        float v = __ldg(fp + c * NPIX);
        ull v2 = pack2(v, v);
        const ulonglong2* wr = (const ulonglong2*)sW[c];
#pragma unroll
        for (int p2 = 0; p2 < 16; ++p2) {
            ulonglong2 w = wr[p2];
            acc2[2 * p2]     = ffma2(v2, w.x, acc2[2 * p2]);
            acc2[2 * p2 + 1] = ffma2(v2, w.y, acc2[2 * p2 + 1]);
        }
    }

    uint4* outp = g_Ph + (((size_t)b * 8) << 14) + pix;
#pragma unroll
    for (int c8 = 0; c8 < 8; ++c8) {
        float f0, f1, f2, f3, f4, f5, f6, f7;
        unpack2(acc2[c8 * 4 + 0], f0, f1);
        unpack2(acc2[c8 * 4 + 1], f2, f3);
        unpack2(acc2[c8 * 4 + 2], f4, f5);
        unpack2(acc2[c8 * 4 + 3], f6, f7);
        __half2 h0 = __floats2half2_rn(f0, f1);
        __half2 h1 = __floats2half2_rn(f2, f3);
        __half2 h2 = __floats2half2_rn(f4, f5);
        __half2 h3 = __floats2half2_rn(f6, f7);
        uint4 o;
        o.x = *(unsigned*)&h0; o.y = *(unsigned*)&h1;
        o.z = *(unsigned*)&h2; o.w = *(unsigned*)&h3;
        outp[(size_t)c8 << 14] = o;
    }
}

// ---------------------------------------------------------
// Main: 1 voxel per thread (gz fastest), LDS.128 weight reads, fp16 taps,
// packed f32x2 MLP. launch_bounds(256,3) keeps 3 blocks/SM resident.
__global__ void __launch_bounds__(256, 3) k_main(const float* __restrict__ pelvis,
                                                 const float* __restrict__ Kmat,
                                                 const float* __restrict__ bbx,
                                                 const float* __restrict__ W1,
                                                 const float* __restrict__ b1,
                                                 const float* __restrict__ W2,
                                                 const float* __restrict__ b2,
                                                 float* __restrict__ outp) {
    __shared__ ulonglong2 sW1xy[32];     // (xpair, ypair) per channel-pair
    __shared__ ulonglong2 sW1zb[32];     // (zpair, b1pair)
    __shared__ ulonglong2 sW2v[64][3];   // row j: 12 floats as 3 x ulonglong2
    __shared__ float sB2[12];
    __shared__ float sred[8][7];

    int t = threadIdx.x;
    if (t < 32) {
        ulonglong2 xy, zb;
        xy.x = pack2(W1[2 * t],       W1[2 * t + 1]);
        xy.y = pack2(W1[64 + 2 * t],  W1[64 + 2 * t + 1]);
        zb.x = pack2(W1[128 + 2 * t], W1[128 + 2 * t + 1]);
        zb.y = pack2(b1[2 * t],       b1[2 * t + 1]);
        sW1xy[t] = xy; sW1zb[t] = zb;
    }
    if (t >= 64 && t < 64 + 192) {
        int i = t - 64;                  // 0..191 = 64 rows x 3 comps
        int j = i / 3, comp = i % 3;
        const float* wr = W2 + j * 12 + comp * 4;
        ulonglong2 w;
        w.x = pack2(wr[0], wr[1]);
        w.y = pack2(wr[2], wr[3]);
        sW2v[j][comp] = w;
    }
    if (t < 12) sB2[t] = b2[t];
    __syncthreads();

    int b = blockIdx.y;
    int g = blockIdx.x * 256 + t;

    float ax = pelvis[b * 3 + 0], ay = pelvis[b * 3 + 1], az = pelvis[b * 3 + 2];
    int anyNb = g_anyNearby[b];
    int v0x = (int)floorf(ax / VSC) - (Gq / 2);
    int v0y = (int)floorf(ay / VSC) - (Gq / 2);
    int v0z = (int)floorf(az / VSC) - (Gq / 2);

    int gx = g >> 12, gy = (g >> 6) & 63, gz = g & 63;
    float cxv = (float)(v0x + gx) * VSC + VSC * 0.5f;
    float cyv = (float)(v0y + gy) * VSC + VSC * 0.5f;
    float czv = (float)(v0z + gz) * VSC + VSC * 0.5f;

    float fx = Kmat[b * 9 + 0], cx0 = Kmat[b * 9 + 2];
    float fy = Kmat[b * 9 + 4], cy0 = Kmat[b * 9 + 5];
    float l = bbx[b * 4 + 0], tp = bbx[b * 4 + 1];
    float r = bbx[b * 4 + 2], bt = bbx[b * 4 + 3];

    float invz = 1.0f / czv;
    float u  = cxv * invz * fx + cx0;
    float vp = cyv * invz * fy + cy0;
    float U = (u - l) / (r - l) * (float)(HW - 1);
    float V = (vp - tp) / (bt - tp) * (float)(HW - 1);

    float x0f = floorf(U), y0f = floorf(V);
    float wx = U - x0f, wy = V - y0f;
    int x0 = (int)x0f, y0 = (int)y0f;
    int x1 = x0 + 1, y1 = y0 + 1;
    bool okx0 = (x0 >= 0 && x0 <= HW - 1), okx1 = (x1 >= 0 && x1 <= HW - 1);
    bool oky0 = (y0 >= 0 && y0 <= HW - 1), oky1 = (y1 >= 0 && y1 <= HW - 1);
    int x0c = min(max(x0, 0), HW - 1), x1c = min(max(x1, 0), HW - 1);
    int y0c = min(max(y0, 0), HW - 1), y1c = min(max(y1, 0), HW - 1);

    float w00 = (1.0f - wx) * (1.0f - wy) * ((okx0 && oky0) ? 1.0f : 0.0f);
    float w10 = wx * (1.0f - wy)          * ((okx1 && oky0) ? 1.0f : 0.0f);
    float w01 = (1.0f - wx) * wy          * ((okx0 && oky1) ? 1.0f : 0.0f);
    float w11 = wx * wy                   * ((okx1 && oky1) ? 1.0f : 0.0f);

    int pix00 = y0c * HW + x0c, pix10 = y0c * HW + x1c;
    int pix01 = y1c * HW + x0c, pix11 = y1c * HW + x1c;

    ull w00_2 = pack2(w00, w00), w10_2 = pack2(w10, w10);
    ull w01_2 = pack2(w01, w01), w11_2 = pack2(w11, w11);
    float geox = ax - cxv, geoy = ay - cyv, geoz = az - czv;
    ull gx2 = pack2(geox, geox), gy2 = pack2(geoy, geoy), gz2 = pack2(geoz, geoz);

    ull acc2[6] = {0ull, 0ull, 0ull, 0ull, 0ull, 0ull};
    const uint4* Pbase = g_Ph + ((size_t)(b * 8) << 14);

#pragma unroll
    for (int c = 0; c < 8; ++c) {
        const uint4* pl = Pbase + ((size_t)c << 14);
        uint4 q00 = __ldg(pl + pix00);
        uint4 q10 = __ldg(pl + pix10);
        uint4 q01 = __ldg(pl + pix01);
        uint4 q11 = __ldg(pl + pix11);
        const __half2* h00 = (const __half2*)&q00;
        const __half2* h10 = (const __half2*)&q10;
        const __half2* h01 = (const __half2*)&q01;
        const __half2* h11 = (const __half2*)&q11;

#pragma unroll
        for (int jj = 0; jj < 4; ++jj) {
            int p0 = c * 4 + jj;
            ulonglong2 wxy = sW1xy[p0];
            ulonglong2 wzb = sW1zb[p0];

            float2 f00 = __half22float2(h00[jj]);
            float2 f10 = __half22float2(h10[jj]);
            float2 f01 = __half22float2(h01[jj]);
            float2 f11 = __half22float2(h11[jj]);
            ull s = ffma2(w00_2, pack2(f00.x, f00.y),
                    ffma2(w10_2, pack2(f10.x, f10.y),
                    ffma2(w01_2, pack2(f01.x, f01.y),
                    ffma2(w11_2, pack2(f11.x, f11.y), 0ull))));

            ull hp = ffma2(gx2, wxy.x, ffma2(gy2, wxy.y,
                     ffma2(gz2, wzb.x, add2(s, wzb.y))));

            float ha, hb;
            unpack2(hp, ha, hb);
            ha = fmaxf(ha, 0.0f); hb = fmaxf(hb, 0.0f);

            int ch = p0 * 2;
            ulonglong2 wa0 = sW2v[ch][0], wa1 = sW2v[ch][1], wa2 = sW2v[ch][2];
            ulonglong2 wb0 = sW2v[ch + 1][0], wb1 = sW2v[ch + 1][1], wb2 = sW2v[ch + 1][2];
            ull hha = pack2(ha, ha), hhb = pack2(hb, hb);

            acc2[0] = ffma2(hha, wa0.x, ffma2(hhb, wb0.x, acc2[0]));
            acc2[1] = ffma2(hha, wa0.y, ffma2(hhb, wb0.y, acc2[1]));
            acc2[2] = ffma2(hha, wa1.x, ffma2(hhb, wb1.x, acc2[2]));
            acc2[3] = ffma2(hha, wa1.y, ffma2(hhb, wb1.y, acc2[3]));
            acc2[4] = ffma2(hha, wa2.x, ffma2(hhb, wb2.x, acc2[4]));
            acc2[5] = ffma2(hha, wa2.y, ffma2(hhb, wb2.y, acc2[5]));
        }
    }

    float acc[12];
#pragma unroll
    for (int rr = 0; rr < 6; ++rr) {
        unpack2(acc2[rr], acc[2 * rr], acc[2 * rr + 1]);
        acc[2 * rr]     += sB2[2 * rr];
        acc[2 * rr + 1] += sB2[2 * rr + 1];
    }

    // write out[b, g, 0:12]
    float4* op = (float4*)(outp + ((size_t)b * G3q + g) * 12);
    op[0] = make_float4(acc[0], acc[1], acc[2], acc[3]);
    op[1] = make_float4(acc[4], acc[5], acc[6], acc[7]);
    op[2] = make_float4(acc[8], acc[9], acc[10], acc[11]);

    // softmax contributions (shift-free: s = sigmoid in (0,1), exp safe)
    size_t oidx = (size_t)b * G3q + g;
    unsigned char occv = anyNb ? g_occS[oidx] : g_occA[oidx];
    float sg  = 1.0f / (1.0f + expf(-acc[0]));
    float wgt = occv ? expf(sg) : 0.0f;
    float px = cxv + acc[1], py = cyv + acc[2], pz = czv + acc[3];

    float red7[7] = { wgt, wgt * px, wgt * py, wgt * pz, px, py, pz };
#pragma unroll
    for (int i = 0; i < 7; ++i) {
        float vv = red7[i];
        vv += __shfl_xor_sync(0xffffffffu, vv, 16);
        vv += __shfl_xor_sync(0xffffffffu, vv, 8);
        vv += __shfl_xor_sync(0xffffffffu, vv, 4);
        vv += __shfl_xor_sync(0xffffffffu, vv, 2);
        vv += __shfl_xor_sync(0xffffffffu, vv, 1);
        red7[i] = vv;
    }
    int wid = t >> 5, lane = t & 31;
    if (lane == 0) {
#pragma unroll
        for (int i = 0; i < 7; ++i) sred[wid][i] = red7[i];
    }
    __syncthreads();
    if (t < 7) {
        float s = 0.0f;
#pragma unroll
        for (int w = 0; w < 8; ++w) s += sred[w][t];
        atomicAdd(&g_accum[b][t], s);
    }
}

__global__ void k_finalize(const float* __restrict__ pelvis,
                           float* __restrict__ refined) {
    int b = threadIdx.x;
    if (b >= Bq) return;
    int anyOcc = g_anyNearby[b] ? g_anyOccS[b] : g_anyOccA[b];
    float wsum = g_accum[b][0];
    float x, y, z;
    if (anyOcc) {
        x = g_accum[b][1] / wsum;
        y = g_accum[b][2] / wsum;
        z = g_accum[b][3] / wsum;
    } else {
        x = g_accum[b][4] / (float)G3q;
        y = g_accum[b][5] / (float)G3q;
        z = g_accum[b][6] / (float)G3q;
    }
    bool bad = isnan(x) || isnan(y) || isnan(z);
    refined[b * 3 + 0] = bad ? pelvis[b * 3 + 0] : x;
    refined[b * 3 + 1] = bad ? pelvis[b * 3 + 1] : y;
    refined[b * 3 + 2] = bad ? pelvis[b * 3 + 2] : z;
}

extern "C" void kernel_launch(void* const* d_in, const int* in_sizes, int n_in,
                              void* d_out, int out_size) {
    const float* points = (const float*)d_in[0];
    const float* fmap   = (const float*)d_in[1];
    const float* pelvis = (const float*)d_in[2];
    const float* Kmat   = (const float*)d_in[3];
    const float* bbx    = (const float*)d_in[4];
    const float* W1     = (const float*)d_in[5];
    const float* b1     = (const float*)d_in[6];
    const float* W2     = (const float*)d_in[7];
    const float* b2     = (const float*)d_in[8];

    float* refined = (float*)d_out;          // (B,3) first
    float* outp    = (float*)d_out + Bq * 3; // (B,G3,12) second

    k_clear<<<G3q / 256, 256>>>();
    k_proj<<<(Bq * NPIX) / 256, 256>>>(fmap, W1);
    k_scatter<<<(Bq * Nq / 4) / 256, 256>>>(points, pelvis);
    k_main<<<dim3(G3q / 256, Bq), 256>>>(pelvis, Kmat, bbx, W1, b1, W2, b2, outp);
    k_finalize<<<1, 32>>>(pelvis, refined);
}

// round 13
// speedup vs baseline: 1.0038x; 1.0038x over previous
#include <cuda_runtime.h>
#include <cuda_fp16.h>
#include <math.h>

#define Bq   4
#define Nq   65536
#define Gq   64
#define G3q  262144          // 64^3
#define CF   32
#define HW   128
#define NPIX (HW * HW)       // 16384
#define VSC  0.05f
#define R2C  1.5625f         // 1.25^2

typedef unsigned long long ull;

// -------- device scratch (no allocations allowed) --------
// P fp16, 8 channel-chunk planes per batch: g_Ph[((b*8+c8)<<14)+pix] = 8 halves
__device__ uint4         g_Ph[(size_t)Bq * 8 * NPIX];      // 8 MB
__device__ unsigned char g_occS[(size_t)Bq * G3q];
__device__ unsigned char g_occA[(size_t)Bq * G3q];
__device__ int           g_anyNearby[Bq];
__device__ int           g_anyOccS[Bq];
__device__ int           g_anyOccA[Bq];
__device__ float         g_accum[Bq][8];

// -------- packed f32x2 helpers --------
__device__ __forceinline__ ull ffma2(ull a, ull b, ull c) {
    ull d; asm("fma.rn.f32x2 %0,%1,%2,%3;" : "=l"(d) : "l"(a), "l"(b), "l"(c)); return d;
}
__device__ __forceinline__ ull add2(ull a, ull b) {
    ull d; asm("add.rn.f32x2 %0,%1,%2;" : "=l"(d) : "l"(a), "l"(b)); return d;
}
__device__ __forceinline__ ull pack2(float lo, float hi) {
    ull d; asm("mov.b64 %0,{%1,%2};" : "=l"(d) : "f"(lo), "f"(hi)); return d;
}
__device__ __forceinline__ void unpack2(ull v, float& lo, float& hi) {
    asm("mov.b64 {%0,%1},%2;" : "=f"(lo), "=f"(hi) : "l"(v));
}

// ---------------------------------------------------------
__global__ void k_clear() {
    int i = blockIdx.x * blockDim.x + threadIdx.x;   // 0 .. 262143
    ((int*)g_occS)[i] = 0;
    ((int*)g_occA)[i] = 0;
    if (i < Bq) { g_anyNearby[i] = 0; g_anyOccS[i] = 0; g_anyOccA[i] = 0; }
    if (i < Bq * 8) ((float*)g_accum)[i] = 0.0f;
}

__device__ __forceinline__ bool is_nearby(float px, float py, float pz,
                                          float ax, float ay, float az) {
    float dx = px - ax, dy = py - ay;
    float d2xy = dx * dx + dy * dy;
    float e0 = pz - (az - 0.5f);
    float e1 = pz - az;
    float e2 = pz - (az + 0.5f);
    float m = fminf(fminf(e0 * e0, e1 * e1), e2 * e2);
    return (d2xy + m) <= R2C;
}

// fused scatter: both occupancy grids + flags (4 points/thread)
__global__ void __launch_bounds__(256) k_scatter(const float* __restrict__ points,
                                                 const float* __restrict__ pelvis) {
    int idx4 = blockIdx.x * 256 + threadIdx.x;
    int b = idx4 >> 14;
    float ax = pelvis[b * 3 + 0], ay = pelvis[b * 3 + 1], az = pelvis[b * 3 + 2];
    int v0x = (int)floorf(ax / VSC) - (Gq / 2);
    int v0y = (int)floorf(ay / VSC) - (Gq / 2);
    int v0z = (int)floorf(az / VSC) - (Gq / 2);

    const float4* pp = (const float4*)(points + (size_t)idx4 * 12);
    float4 A = pp[0], Bv = pp[1], C = pp[2];
    float P[4][3] = { {A.x, A.y, A.z}, {A.w, Bv.x, Bv.y},
                      {Bv.z, Bv.w, C.x}, {C.y, C.z, C.w} };

    bool anyNb = false, anyS = false, anyA = false;
#pragma unroll
    for (int k = 0; k < 4; ++k) {
        float px = P[k][0], py = P[k][1], pz = P[k][2];
        bool nb = is_nearby(px, py, pz, ax, ay, az);
        int lx = (int)floorf(px / VSC) - v0x;
        int ly = (int)floorf(py / VSC) - v0y;
        int lz = (int)floorf(pz / VSC) - v0z;
        bool bounds = (unsigned)lx < (unsigned)Gq && (unsigned)ly < (unsigned)Gq
                    && (unsigned)lz < (unsigned)Gq;
        int cell = (lx << 12) + (ly << 6) + lz;
        if (bounds) {
            g_occA[(size_t)b * G3q + cell] = 1;
            if (nb) g_occS[(size_t)b * G3q + cell] = 1;
        }
        anyNb |= nb; anyS |= (nb && bounds); anyA |= bounds;
    }
    unsigned mN = __ballot_sync(0xffffffffu, anyNb);
    unsigned mS = __ballot_sync(0xffffffffu, anyS);
    unsigned mA = __ballot_sync(0xffffffffu, anyA);
    if ((threadIdx.x & 31) == 0) {
        if (mN) atomicOr(&g_anyNearby[b], 1);
        if (mS) atomicOr(&g_anyOccS[b], 1);
        if (mA) atomicOr(&g_anyOccA[b], 1);
    }
}

// k_proj: one pixel per thread, all 64 channels packed-f32x2; weights in SMEM.
__global__ void __launch_bounds__(256) k_proj(const float* __restrict__ fmap,
                                              const float* __restrict__ W1) {
    __shared__ ull sW[CF][32];   // sW[c][p] = (W1[3+c, 2p], W1[3+c, 2p+1])
    int t = threadIdx.x;
    for (int i = t; i < CF * 32; i += 256) {
        int c = i >> 5, p = i & 31;
        sW[c][p] = pack2(W1[(3 + c) * 64 + 2 * p], W1[(3 + c) * 64 + 2 * p + 1]);
    }
    __syncthreads();

    int idx = blockIdx.x * 256 + t;          // B*NPIX threads
    int pix = idx & (NPIX - 1);
    int b   = idx >> 14;
    const float* fp = fmap + (size_t)b * CF * NPIX + pix;

    ull acc2[32];
#pragma unroll
    for (int p = 0; p < 32; ++p) acc2[p] = 0ull;

#pragma unroll 4
    for (int c = 0; c < CF; ++c) {
        float v = __ldg(fp + c * NPIX);
        ull v2 = pack2(v, v);
        const ulonglong2* wr = (const ulonglong2*)sW[c];
#pragma unroll
        for (int p2 = 0; p2 < 16; ++p2) {
            ulonglong2 w = wr[p2];
            acc2[2 * p2]     = ffma2(v2, w.x, acc2[2 * p2]);
            acc2[2 * p2 + 1] = ffma2(v2, w.y, acc2[2 * p2 + 1]);
        }
    }

    uint4* outp = g_Ph + (((size_t)b * 8) << 14) + pix;
#pragma unroll
    for (int c8 = 0; c8 < 8; ++c8) {
        float f0, f1, f2, f3, f4, f5, f6, f7;
        unpack2(acc2[c8 * 4 + 0], f0, f1);
        unpack2(acc2[c8 * 4 + 1], f2, f3);
        unpack2(acc2[c8 * 4 + 2], f4, f5);
        unpack2(acc2[c8 * 4 + 3], f6, f7);
        __half2 h0 = __floats2half2_rn(f0, f1);
        __half2 h1 = __floats2half2_rn(f2, f3);
        __half2 h2 = __floats2half2_rn(f4, f5);
        __half2 h3 = __floats2half2_rn(f6, f7);
        uint4 o;
        o.x = *(unsigned*)&h0; o.y = *(unsigned*)&h1;
        o.z = *(unsigned*)&h2; o.w = *(unsigned*)&h3;
        outp[(size_t)c8 << 14] = o;
    }
}

// ---------------------------------------------------------
// Main: lanes run along gx (V uniform per warp, bounded U span -> few tap
// lines). Output + occ staged through SMEM to stay coalesced.
// Block: lane = gx_lo(32), warp = gz_lo(8); bx bits: [0]=gx_hi, [1:4)=gz_hi,
// [4:10)=gy. grid.x = 1024.
__global__ void __launch_bounds__(256, 3) k_main(const float* __restrict__ pelvis,
                                                 const float* __restrict__ Kmat,
                                                 const float* __restrict__ bbx,
                                                 const float* __restrict__ W1,
                                                 const float* __restrict__ b1,
                                                 const float* __restrict__ W2,
                                                 const float* __restrict__ b2,
                                                 float* __restrict__ outp) {
    __shared__ ulonglong2 sW1xy[32];      // (xpair, ypair) per channel-pair
    __shared__ ulonglong2 sW1zb[32];      // (zpair, b1pair)
    __shared__ ulonglong2 sW2v[64][3];    // row j: 12 floats as 3 x ulonglong2
    __shared__ float sB2[12];
    __shared__ float sred[8][7];
    __shared__ float sout[8][32][13];     // [gz_w][gx_lane][12] (+pad)
    __shared__ unsigned char socc[32][8]; // [gx_lane][gz_w]

    int t = threadIdx.x;
    int bx = blockIdx.x;
    int b  = blockIdx.y;
    int lane = t & 31, w = t >> 5;

    int anyNb = g_anyNearby[b];
    const unsigned char* occp =
        (anyNb ? g_occS : g_occA) + (size_t)b * G3q;

    if (t < 32) {
        ulonglong2 xy, zb;
        xy.x = pack2(W1[2 * t],       W1[2 * t + 1]);
        xy.y = pack2(W1[64 + 2 * t],  W1[64 + 2 * t + 1]);
        zb.x = pack2(W1[128 + 2 * t], W1[128 + 2 * t + 1]);
        zb.y = pack2(b1[2 * t],       b1[2 * t + 1]);
        sW1xy[t] = xy; sW1zb[t] = zb;
    }
    if (t >= 64 && t < 64 + 192) {
        int i = t - 64;                  // 0..191 = 64 rows x 3 comps
        int j = i / 3, comp = i % 3;
        const float* wr = W2 + j * 12 + comp * 4;
        ulonglong2 wv;
        wv.x = pack2(wr[0], wr[1]);
        wv.y = pack2(wr[2], wr[3]);
        sW2v[j][comp] = wv;
    }
    if (t < 12) sB2[t] = b2[t];
    // stage occupancy bytes coalesced: 32 gx-rows x 8 gz bytes
    if (t < 64) {
        int row = t >> 1, half = t & 1;
        int grow = ((((bx & 1) << 5) | row) << 12) | ((bx >> 4) << 6)
                 | (((bx >> 1) & 7) << 3);
        *(unsigned*)&socc[row][half * 4] =
            *(const unsigned*)(occp + grow + half * 4);
    }
    __syncthreads();

    int gx = ((bx & 1) << 5) | lane;
    int gz = (((bx >> 1) & 7) << 3) | w;
    int gy = bx >> 4;
    int g  = (gx << 12) | (gy << 6) | gz;

    float ax = pelvis[b * 3 + 0], ay = pelvis[b * 3 + 1], az = pelvis[b * 3 + 2];
    int v0x = (int)floorf(ax / VSC) - (Gq / 2);
    int v0y = (int)floorf(ay / VSC) - (Gq / 2);
    int v0z = (int)floorf(az / VSC) - (Gq / 2);

    float cxv = (float)(v0x + gx) * VSC + VSC * 0.5f;
    float cyv = (float)(v0y + gy) * VSC + VSC * 0.5f;
    float czv = (float)(v0z + gz) * VSC + VSC * 0.5f;

    float fx = Kmat[b * 9 + 0], cx0 = Kmat[b * 9 + 2];
    float fy = Kmat[b * 9 + 4], cy0 = Kmat[b * 9 + 5];
    float l = bbx[b * 4 + 0], tp = bbx[b * 4 + 1];
    float r = bbx[b * 4 + 2], bt = bbx[b * 4 + 3];

    float invz = 1.0f / czv;
    float u  = cxv * invz * fx + cx0;
    float vp = cyv * invz * fy + cy0;
    float U = (u - l) / (r - l) * (float)(HW - 1);
    float V = (vp - tp) / (bt - tp) * (float)(HW - 1);

    float x0f = floorf(U), y0f = floorf(V);
    float wx = U - x0f, wy = V - y0f;
    int x0 = (int)x0f, y0 = (int)y0f;
    int x1 = x0 + 1, y1 = y0 + 1;
    bool okx0 = (x0 >= 0 && x0 <= HW - 1), okx1 = (x1 >= 0 && x1 <= HW - 1);
    bool oky0 = (y0 >= 0 && y0 <= HW - 1), oky1 = (y1 >= 0 && y1 <= HW - 1);
    int x0c = min(max(x0, 0), HW - 1), x1c = min(max(x1, 0), HW - 1);
    int y0c = min(max(y0, 0), HW - 1), y1c = min(max(y1, 0), HW - 1);

    float w00 = (1.0f - wx) * (1.0f - wy) * ((okx0 && oky0) ? 1.0f : 0.0f);
    float w10 = wx * (1.0f - wy)          * ((okx1 && oky0) ? 1.0f : 0.0f);
    float w01 = (1.0f - wx) * wy          * ((okx0 && oky1) ? 1.0f : 0.0f);
    float w11 = wx * wy                   * ((okx1 && oky1) ? 1.0f : 0.0f);

    int pix00 = y0c * HW + x0c, pix10 = y0c * HW + x1c;
    int pix01 = y1c * HW + x0c, pix11 = y1c * HW + x1c;

    ull w00_2 = pack2(w00, w00), w10_2 = pack2(w10, w10);
    ull w01_2 = pack2(w01, w01), w11_2 = pack2(w11, w11);
    float geox = ax - cxv, geoy = ay - cyv, geoz = az - czv;
    ull gx2 = pack2(geox, geox), gy2 = pack2(geoy, geoy), gz2 = pack2(geoz, geoz);

    ull acc2[6] = {0ull, 0ull, 0ull, 0ull, 0ull, 0ull};
    const uint4* Pbase = g_Ph + ((size_t)(b * 8) << 14);

#pragma unroll
    for (int c = 0; c < 8; ++c) {
        const uint4* pl = Pbase + ((size_t)c << 14);
        uint4 q00 = __ldg(pl + pix00);
        uint4 q10 = __ldg(pl + pix10);
        uint4 q01 = __ldg(pl + pix01);
        uint4 q11 = __ldg(pl + pix11);
        const __half2* h00 = (const __half2*)&q00;
        const __half2* h10 = (const __half2*)&q10;
        const __half2* h01 = (const __half2*)&q01;
        const __half2* h11 = (const __half2*)&q11;

#pragma unroll
        for (int jj = 0; jj < 4; ++jj) {
            int p0 = c * 4 + jj;
            ulonglong2 wxy = sW1xy[p0];
            ulonglong2 wzb = sW1zb[p0];

            float2 f00 = __half22float2(h00[jj]);
            float2 f10 = __half22float2(h10[jj]);
            float2 f01 = __half22float2(h01[jj]);
            float2 f11 = __half22float2(h11[jj]);
            ull s = ffma2(w00_2, pack2(f00.x, f00.y),
                    ffma2(w10_2, pack2(f10.x, f10.y),
                    ffma2(w01_2, pack2(f01.x, f01.y),
                    ffma2(w11_2, pack2(f11.x, f11.y), 0ull))));

            ull hp = ffma2(gx2, wxy.x, ffma2(gy2, wxy.y,
                     ffma2(gz2, wzb.x, add2(s, wzb.y))));

            float ha, hb;
            unpack2(hp, ha, hb);
            ha = fmaxf(ha, 0.0f); hb = fmaxf(hb, 0.0f);

            int ch = p0 * 2;
            ulonglong2 wa0 = sW2v[ch][0], wa1 = sW2v[ch][1], wa2 = sW2v[ch][2];
            ulonglong2 wb0 = sW2v[ch + 1][0], wb1 = sW2v[ch + 1][1], wb2 = sW2v[ch + 1][2];
            ull hha = pack2(ha, ha), hhb = pack2(hb, hb);

            acc2[0] = ffma2(hha, wa0.x, ffma2(hhb, wb0.x, acc2[0]));
            acc2[1] = ffma2(hha, wa0.y, ffma2(hhb, wb0.y, acc2[1]));
            acc2[2] = ffma2(hha, wa1.x, ffma2(hhb, wb1.x, acc2[2]));
            acc2[3] = ffma2(hha, wa1.y, ffma2(hhb, wb1.y, acc2[3]));
            acc2[4] = ffma2(hha, wa2.x, ffma2(hhb, wb2.x, acc2[4]));
            acc2[5] = ffma2(hha, wa2.y, ffma2(hhb, wb2.y, acc2[5]));
        }
    }

    float acc[12];
#pragma unroll
    for (int rr = 0; rr < 6; ++rr) {
        unpack2(acc2[rr], acc[2 * rr], acc[2 * rr + 1]);
        acc[2 * rr]     += sB2[2 * rr];
        acc[2 * rr + 1] += sB2[2 * rr + 1];
    }

    // stage result into SMEM for coalesced writeback
#pragma unroll
    for (int k = 0; k < 12; ++k) sout[w][lane][k] = acc[k];

    // softmax contributions (shift-free: s = sigmoid in (0,1), exp safe)
    unsigned char occv = socc[lane][w];
    float sg  = 1.0f / (1.0f + expf(-acc[0]));
    float wgt = occv ? expf(sg) : 0.0f;
    float px = cxv + acc[1], py = cyv + acc[2], pz = czv + acc[3];

    float red7[7] = { wgt, wgt * px, wgt * py, wgt * pz, px, py, pz };
#pragma unroll
    for (int i = 0; i < 7; ++i) {
        float vv = red7[i];
        vv += __shfl_xor_sync(0xffffffffu, vv, 16);
        vv += __shfl_xor_sync(0xffffffffu, vv, 8);
        vv += __shfl_xor_sync(0xffffffffu, vv, 4);
        vv += __shfl_xor_sync(0xffffffffu, vv, 2);
        vv += __shfl_xor_sync(0xffffffffu, vv, 1);
        red7[i] = vv;
    }
    if ((t & 31) == 0) {
#pragma unroll
        for (int i = 0; i < 7; ++i) sred[w][i] = red7[i];
    }
    __syncthreads();

    if (t < 7) {
        float s = 0.0f;
#pragma unroll
        for (int wq = 0; wq < 8; ++wq) s += sred[wq][t];
        atomicAdd(&g_accum[b][t], s);
    }

    // coalesced writeback: 32 gx-rows x (8 gz x 12 floats) = 768 float4
#pragma unroll
    for (int k3 = 0; k3 < 3; ++k3) {
        int idx = t * 3 + k3;            // 0..767
        int row = idx / 24;              // gx-lane index
        int j   = idx % 24;              // float4 within row
        int gzw = j / 3;
        int k   = (j % 3) * 4;
        int grow = ((((bx & 1) << 5) | row) << 12) | ((bx >> 4) << 6)
                 | (((bx >> 1) & 7) << 3);
        float4 v = make_float4(sout[gzw][row][k],     sout[gzw][row][k + 1],
                               sout[gzw][row][k + 2], sout[gzw][row][k + 3]);
        *(float4*)(outp + ((size_t)b * G3q + grow) * 12 + j * 4) = v;
    }
}

__global__ void k_finalize(const float* __restrict__ pelvis,
                           float* __restrict__ refined) {
    int b = threadIdx.x;
    if (b >= Bq) return;
    int anyOcc = g_anyNearby[b] ? g_anyOccS[b] : g_anyOccA[b];
    float wsum = g_accum[b][0];
    float x, y, z;
    if (anyOcc) {
        x = g_accum[b][1] / wsum;
        y = g_accum[b][2] / wsum;
        z = g_accum[b][3] / wsum;
    } else {
        x = g_accum[b][4] / (float)G3q;
        y = g_accum[b][5] / (float)G3q;
        z = g_accum[b][6] / (float)G3q;
    }
    bool bad = isnan(x) || isnan(y) || isnan(z);
    refined[b * 3 + 0] = bad ? pelvis[b * 3 + 0] : x;
    refined[b * 3 + 1] = bad ? pelvis[b * 3 + 1] : y;
    refined[b * 3 + 2] = bad ? pelvis[b * 3 + 2] : z;
}

extern "C" void kernel_launch(void* const* d_in, const int* in_sizes, int n_in,
                              void* d_out, int out_size) {
    const float* points = (const float*)d_in[0];
    const float* fmap   = (const float*)d_in[1];
    const float* pelvis = (const float*)d_in[2];
    const float* Kmat   = (const float*)d_in[3];
    const float* bbx    = (const float*)d_in[4];
    const float* W1     = (const float*)d_in[5];
    const float* b1     = (const float*)d_in[6];
    const float* W2     = (const float*)d_in[7];
    const float* b2     = (const float*)d_in[8];

    float* refined = (float*)d_out;          // (B,3) first
    float* outp    = (float*)d_out + Bq * 3; // (B,G3,12) second

    k_clear<<<G3q / 256, 256>>>();
    k_proj<<<(Bq * NPIX) / 256, 256>>>(fmap, W1);
    k_scatter<<<(Bq * Nq / 4) / 256, 256>>>(points, pelvis);
    k_main<<<dim3(1024, Bq), 256>>>(pelvis, Kmat, bbx, W1, b1, W2, b2, outp);
    k_finalize<<<1, 32>>>(pelvis, refined);
}